// round 12
// baseline (speedup 1.0000x reference)
#include <cuda_runtime.h>

#define QN 100
#define BC 512
#define HH 256
#define WW 256
#define HW (HH*WW)
#define QOUT (QN*BC)   // 51200

// tile config
#define NT 288
#define TH 32
#define TW 64
#define PH 36         // value rows (halo 2)
#define PW 72         // value padded width (stride 288B)
#define SH 34         // stage rows (halo 1)
#define SWP 68        // stage padded width (stride 272B); cols [0,66) meaningful

__device__ float g_conv1d[BC * 18];

// ---- packed f32x2 helpers (FFMA2 only reachable via PTX) ----
#define PACK2(d, lo, hi)  asm("mov.b64 %0, {%1, %2};" : "=l"(d) : "f"(lo), "f"(hi))
#define UNPACK2(lo, hi, v) asm("mov.b64 {%0, %1}, %2;" : "=f"(lo), "=f"(hi) : "l"(v))
#define FMA2(d, a, b, c)  asm("fma.rn.f32x2 %0, %1, %2, %3;" : "=l"(d) : "l"(a), "l"(b), "l"(c))
#define MUL2(d, a, b)     asm("mul.rn.f32x2 %0, %1, %2;" : "=l"(d) : "l"(a), "l"(b))

typedef unsigned long long u64t;

// ---------------------------------------------------------------------------
// Kernel A: weight generation + q projection. One thread per (b,c),
// lane-consecutive bc -> coalesced query reads and out_q writes.
// ---------------------------------------------------------------------------
__global__ void __launch_bounds__(32) k_w(
    const float* __restrict__ query,   // (100, 8, 64)
    const float* __restrict__ Wl,      // (18, 100)
    const float* __restrict__ bl,      // (18,)
    const float* __restrict__ Wd,      // (100, 18)
    const float* __restrict__ bd,      // (100,)
    float* __restrict__ out_q)         // (100, 512) at start of d_out
{
    const int bc = blockIdx.x * 32 + threadIdx.x;   // grid 16

    float acc[18];
#pragma unroll
    for (int k = 0; k < 18; k++) acc[k] = bl[k];

#pragma unroll 4
    for (int q = 0; q < QN; q++) {
        float qv = query[q * BC + bc];
#pragma unroll
        for (int k = 0; k < 18; k++) acc[k] += qv * Wl[k * QN + q];
    }

#pragma unroll
    for (int k = 0; k < 18; k++) g_conv1d[bc * 18 + k] = acc[k];

    for (int n = 0; n < QN; n++) {
        float s = bd[n];
#pragma unroll
        for (int k = 0; k < 18; k++) s += acc[k] * Wd[n * 18 + k];
        out_q[n * BC + bc] = s;
    }
}

// ---------------------------------------------------------------------------
// Kernel B: fused depthwise chain; 2 px/thread, f32x2 packed math.
// ---------------------------------------------------------------------------
__global__ void __launch_bounds__(NT, 2) k_main(
    const float* __restrict__ value,
    float* __restrict__ out)
{
    __shared__ float sv [PH][PW];
    __shared__ float syt[SH][SWP];
    __shared__ float sdf[SH][SWP];
    __shared__ float svd[SH][SWP];
    __shared__ float swt[18];

    const int bc  = blockIdx.z;
    const int h0  = blockIdx.y * TH;
    const int w0  = blockIdx.x * TW;
    const int tid = threadIdx.x;

    if (tid < 18) swt[tid] = g_conv1d[bc * 18 + tid];

    // ---- stage1: load value with halo-2, zero pad; fill all 72 cols ----
    {
        const int col = tid % PW;      // 0..71
        const int g   = tid / PW;      // 0..3
        const int ph0 = g * 9;
        const int gw  = w0 - 2 + col;
        const bool wok = (col < 68) && ((unsigned)gw < WW);
        const float* src = value + (size_t)bc * HW + (h0 - 2 + ph0) * WW + gw;
#pragma unroll
        for (int r = 0; r < 9; r++) {
            int gh = h0 - 2 + ph0 + r;
            float v = 0.f;
            if (wok && (unsigned)gh < HH) v = src[r * WW];
            sv[ph0 + r][col] = v;
        }
    }
    __syncthreads();

    // ---- stage2: y_temp / diff / vd, 2 stage-cols per thread, sliding ----
    if (tid < 272) {
        const int pc  = tid % 34;                    // pair col: stage cols 2pc,2pc+1
        const int g   = tid / 34;                    // 0..7
        const int len = (g < 2) ? 5 : 4;
        const int sy0 = g * 4 + ((g < 2) ? g : 2);   // 0,5,10,14,...,30
        const int s   = 2 * pc;

        u64t f[9];
#pragma unroll
        for (int k = 0; k < 9; k++) PACK2(f[k], swt[k], swt[k]);

        const int gwlo = w0 - 1 + s;
        const bool okLo = (unsigned)gwlo < WW;
        const bool okHi = (unsigned)(gwlo + 1) < WW;

        const float* base = &sv[sy0][s];
        u64t a0,a1,a2, b0,b1,b2;
        {
            float2 L = *(const float2*)base, R = *(const float2*)(base + 2);
            PACK2(a0, L.x, L.y); PACK2(a1, L.y, R.x); PACK2(a2, R.x, R.y);
            base += PW;
            L = *(const float2*)base; R = *(const float2*)(base + 2);
            PACK2(b0, L.x, L.y); PACK2(b1, L.y, R.x); PACK2(b2, R.x, R.y);
            base += PW;
        }
#pragma unroll
        for (int r = 0; r < 5; r++) {
            if (r < len) {
                u64t c0, c1, c2;
                float2 L = *(const float2*)base, R = *(const float2*)(base + 2);
                PACK2(c0, L.x, L.y); PACK2(c1, L.y, R.x); PACK2(c2, R.x, R.y);
                base += PW;

                u64t yt;
                MUL2(yt, f[0], a0);
                FMA2(yt, f[1], a1, yt); FMA2(yt, f[2], a2, yt);
                FMA2(yt, f[3], b0, yt); FMA2(yt, f[4], b1, yt);
                FMA2(yt, f[5], b2, yt); FMA2(yt, f[6], c0, yt);
                FMA2(yt, f[7], c1, yt); FMA2(yt, f[8], c2, yt);

                float y0, y1, v0, v1;
                UNPACK2(y0, y1, yt);
                UNPACK2(v0, v1, b1);        // centers sv[s+1], sv[s+2]

                const int sy = sy0 + r;
                const int gh = h0 - 1 + sy;
                const bool rok = (unsigned)gh < HH;
                float t0 = v0 - y0, t1 = v1 - y1;
                float d0 = (rok && okLo) ? __expf(-t0 * t0) : 0.f;
                float d1 = (rok && okHi) ? __expf(-t1 * t1) : 0.f;

                *(float2*)&syt[sy][s] = make_float2(y0, y1);
                *(float2*)&sdf[sy][s] = make_float2(d0, d1);
                *(float2*)&svd[sy][s] = make_float2(v0 * d0, v1 * d1);

                a0 = b0; a1 = b1; a2 = b2;
                b0 = c0; b1 = c1; b2 = c2;
            }
        }
    }
    __syncthreads();

    // ---- stage3: second convs + combine, 2 px/thread, sliding 4 rows ----
    if (tid < 256) {
        const int pc  = tid & 31;     // output cols 2pc, 2pc+1
        const int g   = tid >> 5;     // rows g*4 .. g*4+3
        const int s   = 2 * pc;       // stage col base
        const int hl0 = g * 4;

        u64t pa[9], pr[9];
#pragma unroll
        for (int k = 0; k < 9; k++) {
            float w = swt[9 + k], a = fabsf(w);
            PACK2(pa[k], a, a);
        }
        {
            float m0 = -(swt[9]  + swt[15]);
            float m1 = -(swt[10] + swt[16]);
            float m2 = -(swt[11] + swt[17]);
            PACK2(pr[0], swt[9],  swt[9]);  PACK2(pr[1], swt[10], swt[10]);
            PACK2(pr[2], swt[11], swt[11]);
            PACK2(pr[3], m0, m0); PACK2(pr[4], m1, m1); PACK2(pr[5], m2, m2);
            PACK2(pr[6], swt[15], swt[15]); PACK2(pr[7], swt[16], swt[16]);
            PACK2(pr[8], swt[17], swt[17]);
        }

        const float* pd = &sdf[hl0][s];
        const float* px = &svd[hl0][s];
        u64t da0,da1,da2, db0,db1,db2;
        u64t xa0,xa1,xa2, xb0,xb1,xb2;
        {
            float2 L = *(const float2*)pd, R = *(const float2*)(pd + 2);
            PACK2(da0, L.x, L.y); PACK2(da1, L.y, R.x); PACK2(da2, R.x, R.y);
            L = *(const float2*)px; R = *(const float2*)(px + 2);
            PACK2(xa0, L.x, L.y); PACK2(xa1, L.y, R.x); PACK2(xa2, R.x, R.y);
            pd += SWP; px += SWP;
            L = *(const float2*)pd; R = *(const float2*)(pd + 2);
            PACK2(db0, L.x, L.y); PACK2(db1, L.y, R.x); PACK2(db2, R.x, R.y);
            L = *(const float2*)px; R = *(const float2*)(px + 2);
            PACK2(xb0, L.x, L.y); PACK2(xb1, L.y, R.x); PACK2(xb2, R.x, R.y);
            pd += SWP; px += SWP;
        }

        float* ybase = out + QOUT + (size_t)bc * HW + (size_t)(h0 + hl0) * WW + (w0 + s);

#pragma unroll
        for (int r = 0; r < 4; r++) {
            u64t dc0,dc1,dc2, xc0,xc1,xc2;
            {
                float2 L = *(const float2*)pd, R = *(const float2*)(pd + 2);
                PACK2(dc0, L.x, L.y); PACK2(dc1, L.y, R.x); PACK2(dc2, R.x, R.y);
                L = *(const float2*)px; R = *(const float2*)(px + 2);
                PACK2(xc0, L.x, L.y); PACK2(xc1, L.y, R.x); PACK2(xc2, R.x, R.y);
                pd += SWP; px += SWP;
            }

            u64t a9, ar;
            MUL2(a9, pa[0], da0);
            FMA2(a9, pa[1], da1, a9); FMA2(a9, pa[2], da2, a9);
            FMA2(a9, pa[3], db0, a9); FMA2(a9, pa[4], db1, a9);
            FMA2(a9, pa[5], db2, a9); FMA2(a9, pa[6], dc0, a9);
            FMA2(a9, pa[7], dc1, a9); FMA2(a9, pa[8], dc2, a9);

            MUL2(ar, pr[0], xa0);
            FMA2(ar, pr[1], xa1, ar); FMA2(ar, pr[2], xa2, ar);
            FMA2(ar, pr[3], xb0, ar); FMA2(ar, pr[4], xb1, ar);
            FMA2(ar, pr[5], xb2, ar); FMA2(ar, pr[6], xc0, ar);
            FMA2(ar, pr[7], xc1, ar); FMA2(ar, pr[8], xc2, ar);

            float a9lo, a9hi, arlo, arhi;
            UNPACK2(a9lo, a9hi, a9);
            UNPACK2(arlo, arhi, ar);

            float yt0 = syt[hl0 + r + 1][s + 1];
            float yt1 = syt[hl0 + r + 1][s + 2];
            float v0 = yt0 - __fdividef(arlo, a9lo + 1e-10f);
            float v1 = yt1 - __fdividef(arhi, a9hi + 1e-10f);
            *(float2*)ybase = make_float2(v0, v1);
            ybase += WW;

            da0 = db0; da1 = db1; da2 = db2;
            db0 = dc0; db1 = dc1; db2 = dc2;
            xa0 = xb0; xa1 = xb1; xa2 = xb2;
            xb0 = xc0; xb1 = xc1; xb2 = xc2;
        }
    }
}

// ---------------------------------------------------------------------------
extern "C" void kernel_launch(void* const* d_in, const int* in_sizes, int n_in,
                              void* d_out, int out_size)
{
    (void)in_sizes; (void)n_in; (void)out_size;
    const float* query = (const float*)d_in[0];
    const float* value = (const float*)d_in[1];
    const float* Wl = (const float*)d_in[5];
    const float* bl = (const float*)d_in[6];
    const float* Wd = (const float*)d_in[7];
    const float* bd = (const float*)d_in[8];
    float* out = (float*)d_out;

    k_w<<<BC / 32, 32>>>(query, Wl, bl, Wd, bd, out);

    dim3 grid(WW / TW, HH / TH, BC);
    k_main<<<grid, NT>>>(value, out);
}

// round 13
// speedup vs baseline: 1.0111x; 1.0111x over previous
#include <cuda_runtime.h>

#define QN 100
#define BC 512
#define HH 256
#define WW 256
#define HW (HH*WW)
#define QOUT (QN*BC)   // 51200

// tile config
#define NT 288
#define TH 32
#define TW 64
#define PH 36         // value rows (halo 2)
#define PW 72         // value padded width (stride 288B)
#define SH 34         // stage rows (halo 1)
#define SWP 68        // stage padded width (stride 272B); cols [0,66) meaningful

__device__ float g_conv1d[BC * 18];

// ---- packed f32x2 helpers (FFMA2 only reachable via PTX) ----
#define PACK2(d, lo, hi)  asm("mov.b64 %0, {%1, %2};" : "=l"(d) : "f"(lo), "f"(hi))
#define UNPACK2(lo, hi, v) asm("mov.b64 {%0, %1}, %2;" : "=f"(lo), "=f"(hi) : "l"(v))
#define FMA2(d, a, b, c)  asm("fma.rn.f32x2 %0, %1, %2, %3;" : "=l"(d) : "l"(a), "l"(b), "l"(c))
#define MUL2(d, a, b)     asm("mul.rn.f32x2 %0, %1, %2;" : "=l"(d) : "l"(a), "l"(b))

typedef unsigned long long u64t;

// ---------------------------------------------------------------------------
// Kernel A: weight generation + q projection. One thread per (b,c),
// lane-consecutive bc -> coalesced query reads and out_q writes.
// ---------------------------------------------------------------------------
__global__ void __launch_bounds__(32) k_w(
    const float* __restrict__ query,   // (100, 8, 64)
    const float* __restrict__ Wl,      // (18, 100)
    const float* __restrict__ bl,      // (18,)
    const float* __restrict__ Wd,      // (100, 18)
    const float* __restrict__ bd,      // (100,)
    float* __restrict__ out_q)         // (100, 512) at start of d_out
{
    const int bc = blockIdx.x * 32 + threadIdx.x;   // grid 16

    float acc[18];
#pragma unroll
    for (int k = 0; k < 18; k++) acc[k] = bl[k];

#pragma unroll 4
    for (int q = 0; q < QN; q++) {
        float qv = query[q * BC + bc];
#pragma unroll
        for (int k = 0; k < 18; k++) acc[k] += qv * Wl[k * QN + q];
    }

#pragma unroll
    for (int k = 0; k < 18; k++) g_conv1d[bc * 18 + k] = acc[k];

    for (int n = 0; n < QN; n++) {
        float s = bd[n];
#pragma unroll
        for (int k = 0; k < 18; k++) s += acc[k] * Wd[n * 18 + k];
        out_q[n * BC + bc] = s;
    }
}

// ---------------------------------------------------------------------------
// Kernel B: fused depthwise chain; 2 px/thread, f32x2 packed math.
// ---------------------------------------------------------------------------
__global__ void __launch_bounds__(NT, 2) k_main(
    const float* __restrict__ value,
    float* __restrict__ out)
{
    __shared__ float sv [PH][PW];
    __shared__ float syt[SH][SWP];
    __shared__ float sdf[SH][SWP];
    __shared__ float svd[SH][SWP];
    __shared__ float swt[18];

    const int bc  = blockIdx.z;
    const int h0  = blockIdx.y * TH;
    const int w0  = blockIdx.x * TW;
    const int tid = threadIdx.x;

    if (tid < 18) swt[tid] = g_conv1d[bc * 18 + tid];

    // ---- stage1: load value with halo-2, zero pad; fill all 72 cols ----
    {
        const int col = tid % PW;      // 0..71
        const int g   = tid / PW;      // 0..3
        const int ph0 = g * 9;
        const int gw  = w0 - 2 + col;
        const bool wok = (col < 68) && ((unsigned)gw < WW);
        const float* src = value + (size_t)bc * HW + (h0 - 2 + ph0) * WW + gw;
#pragma unroll
        for (int r = 0; r < 9; r++) {
            int gh = h0 - 2 + ph0 + r;
            float v = 0.f;
            if (wok && (unsigned)gh < HH) v = src[r * WW];
            sv[ph0 + r][col] = v;
        }
    }
    __syncthreads();

    // ---- stage2: y_temp / diff / vd, 2 stage-cols per thread, sliding ----
    if (tid < 272) {
        const int pc  = tid % 34;                    // pair col: stage cols 2pc,2pc+1
        const int g   = tid / 34;                    // 0..7
        const int len = (g < 2) ? 5 : 4;
        const int sy0 = g * 4 + ((g < 2) ? g : 2);   // 0,5,10,14,...,30
        const int s   = 2 * pc;

        u64t f[9];
#pragma unroll
        for (int k = 0; k < 9; k++) PACK2(f[k], swt[k], swt[k]);

        const int gwlo = w0 - 1 + s;
        const bool okLo = (unsigned)gwlo < WW;
        const bool okHi = (unsigned)(gwlo + 1) < WW;

        const float* base = &sv[sy0][s];
        u64t a0,a1,a2, b0,b1,b2;
        {
            float2 L = *(const float2*)base, R = *(const float2*)(base + 2);
            PACK2(a0, L.x, L.y); PACK2(a1, L.y, R.x); PACK2(a2, R.x, R.y);
            base += PW;
            L = *(const float2*)base; R = *(const float2*)(base + 2);
            PACK2(b0, L.x, L.y); PACK2(b1, L.y, R.x); PACK2(b2, R.x, R.y);
            base += PW;
        }
#pragma unroll
        for (int r = 0; r < 5; r++) {
            if (r < len) {
                u64t c0, c1, c2;
                float2 L = *(const float2*)base, R = *(const float2*)(base + 2);
                PACK2(c0, L.x, L.y); PACK2(c1, L.y, R.x); PACK2(c2, R.x, R.y);
                base += PW;

                u64t yt;
                MUL2(yt, f[0], a0);
                FMA2(yt, f[1], a1, yt); FMA2(yt, f[2], a2, yt);
                FMA2(yt, f[3], b0, yt); FMA2(yt, f[4], b1, yt);
                FMA2(yt, f[5], b2, yt); FMA2(yt, f[6], c0, yt);
                FMA2(yt, f[7], c1, yt); FMA2(yt, f[8], c2, yt);

                float y0, y1, v0, v1;
                UNPACK2(y0, y1, yt);
                UNPACK2(v0, v1, b1);        // centers sv[s+1], sv[s+2]

                const int sy = sy0 + r;
                const int gh = h0 - 1 + sy;
                const bool rok = (unsigned)gh < HH;
                float t0 = v0 - y0, t1 = v1 - y1;
                float d0 = (rok && okLo) ? __expf(-t0 * t0) : 0.f;
                float d1 = (rok && okHi) ? __expf(-t1 * t1) : 0.f;

                *(float2*)&syt[sy][s] = make_float2(y0, y1);
                *(float2*)&sdf[sy][s] = make_float2(d0, d1);
                *(float2*)&svd[sy][s] = make_float2(v0 * d0, v1 * d1);

                a0 = b0; a1 = b1; a2 = b2;
                b0 = c0; b1 = c1; b2 = c2;
            }
        }
    }
    __syncthreads();

    // ---- stage3: second convs + combine, 2 px/thread, sliding 4 rows ----
    if (tid < 256) {
        const int pc  = tid & 31;     // output cols 2pc, 2pc+1
        const int g   = tid >> 5;     // rows g*4 .. g*4+3
        const int s   = 2 * pc;       // stage col base
        const int hl0 = g * 4;

        u64t pa[9], pr[9];
#pragma unroll
        for (int k = 0; k < 9; k++) {
            float w = swt[9 + k], a = fabsf(w);
            PACK2(pa[k], a, a);
        }
        {
            float m0 = -(swt[9]  + swt[15]);
            float m1 = -(swt[10] + swt[16]);
            float m2 = -(swt[11] + swt[17]);
            PACK2(pr[0], swt[9],  swt[9]);  PACK2(pr[1], swt[10], swt[10]);
            PACK2(pr[2], swt[11], swt[11]);
            PACK2(pr[3], m0, m0); PACK2(pr[4], m1, m1); PACK2(pr[5], m2, m2);
            PACK2(pr[6], swt[15], swt[15]); PACK2(pr[7], swt[16], swt[16]);
            PACK2(pr[8], swt[17], swt[17]);
        }

        const float* pd = &sdf[hl0][s];
        const float* px = &svd[hl0][s];
        u64t da0,da1,da2, db0,db1,db2;
        u64t xa0,xa1,xa2, xb0,xb1,xb2;
        {
            float2 L = *(const float2*)pd, R = *(const float2*)(pd + 2);
            PACK2(da0, L.x, L.y); PACK2(da1, L.y, R.x); PACK2(da2, R.x, R.y);
            L = *(const float2*)px; R = *(const float2*)(px + 2);
            PACK2(xa0, L.x, L.y); PACK2(xa1, L.y, R.x); PACK2(xa2, R.x, R.y);
            pd += SWP; px += SWP;
            L = *(const float2*)pd; R = *(const float2*)(pd + 2);
            PACK2(db0, L.x, L.y); PACK2(db1, L.y, R.x); PACK2(db2, R.x, R.y);
            L = *(const float2*)px; R = *(const float2*)(px + 2);
            PACK2(xb0, L.x, L.y); PACK2(xb1, L.y, R.x); PACK2(xb2, R.x, R.y);
            pd += SWP; px += SWP;
        }

        float* ybase = out + QOUT + (size_t)bc * HW + (size_t)(h0 + hl0) * WW + (w0 + s);

#pragma unroll
        for (int r = 0; r < 4; r++) {
            u64t dc0,dc1,dc2, xc0,xc1,xc2;
            {
                float2 L = *(const float2*)pd, R = *(const float2*)(pd + 2);
                PACK2(dc0, L.x, L.y); PACK2(dc1, L.y, R.x); PACK2(dc2, R.x, R.y);
                L = *(const float2*)px; R = *(const float2*)(px + 2);
                PACK2(xc0, L.x, L.y); PACK2(xc1, L.y, R.x); PACK2(xc2, R.x, R.y);
                pd += SWP; px += SWP;
            }

            u64t a9, ar;
            MUL2(a9, pa[0], da0);
            FMA2(a9, pa[1], da1, a9); FMA2(a9, pa[2], da2, a9);
            FMA2(a9, pa[3], db0, a9); FMA2(a9, pa[4], db1, a9);
            FMA2(a9, pa[5], db2, a9); FMA2(a9, pa[6], dc0, a9);
            FMA2(a9, pa[7], dc1, a9); FMA2(a9, pa[8], dc2, a9);

            MUL2(ar, pr[0], xa0);
            FMA2(ar, pr[1], xa1, ar); FMA2(ar, pr[2], xa2, ar);
            FMA2(ar, pr[3], xb0, ar); FMA2(ar, pr[4], xb1, ar);
            FMA2(ar, pr[5], xb2, ar); FMA2(ar, pr[6], xc0, ar);
            FMA2(ar, pr[7], xc1, ar); FMA2(ar, pr[8], xc2, ar);

            float a9lo, a9hi, arlo, arhi;
            UNPACK2(a9lo, a9hi, a9);
            UNPACK2(arlo, arhi, ar);

            float yt0 = syt[hl0 + r + 1][s + 1];
            float yt1 = syt[hl0 + r + 1][s + 2];
            float v0 = yt0 - __fdividef(arlo, a9lo + 1e-10f);
            float v1 = yt1 - __fdividef(arhi, a9hi + 1e-10f);
            *(float2*)ybase = make_float2(v0, v1);
            ybase += WW;

            da0 = db0; da1 = db1; da2 = db2;
            db0 = dc0; db1 = dc1; db2 = dc2;
            xa0 = xb0; xa1 = xb1; xa2 = xb2;
            xb0 = xc0; xb1 = xc1; xb2 = xc2;
        }
    }
}

// ---------------------------------------------------------------------------
extern "C" void kernel_launch(void* const* d_in, const int* in_sizes, int n_in,
                              void* d_out, int out_size)
{
    (void)in_sizes; (void)n_in; (void)out_size;
    const float* query = (const float*)d_in[0];
    const float* value = (const float*)d_in[1];
    const float* Wl = (const float*)d_in[5];
    const float* bl = (const float*)d_in[6];
    const float* Wd = (const float*)d_in[7];
    const float* bd = (const float*)d_in[8];
    float* out = (float*)d_out;

    k_w<<<BC / 32, 32>>>(query, Wl, bl, Wd, bd, out);

    dim3 grid(WW / TW, HH / TH, BC);
    k_main<<<grid, NT>>>(value, out);
}